// round 15
// baseline (speedup 1.0000x reference)
#include <cuda_runtime.h>
#include <cuda_fp16.h>
#include <cstdint>

#define NN 512          // nodes (attention axis)
#define TT 32           // time steps
#define HH 8            // heads
#define DD 16           // per-head dim
#define CC 128          // embed

// Attention output: [node][t][h][dpair] as half2-in-u32, row-major = [row R][64]
__device__ uint32_t g_O16[NN*TT*HH*8];
// Pre-converted FC weights, B-operand layout [cpair 64][e 128], fp16 pairs
__device__ uint32_t g_Wh[64*CC];

__device__ __forceinline__ uint32_t packh2(float lo, float hi){
    uint32_t r; asm("cvt.rn.f16x2.f32 %0, %1, %2;" : "=r"(r) : "f"(hi), "f"(lo)); return r;
}
__device__ __forceinline__ uint32_t ex2h2(uint32_t x){
    uint32_t r; asm("ex2.approx.f16x2 %0, %1;" : "=r"(r) : "r"(x)); return r;
}
__device__ __forceinline__ uint32_t hadd2(uint32_t a, uint32_t b){
    uint32_t r; asm("add.f16x2 %0, %1, %2;" : "=r"(r) : "r"(a), "r"(b)); return r;
}
__device__ __forceinline__ float h2sum(uint32_t v){
    __half2 h = *(__half2*)&v;
    return __half2float(__low2half(h)) + __half2float(__high2half(h));
}
__device__ __forceinline__ void mma_f16(float& c0, float& c1, float& c2, float& c3,
                                        uint32_t a0, uint32_t a1, uint32_t a2, uint32_t a3,
                                        uint32_t b0, uint32_t b1){
    asm volatile("mma.sync.aligned.m16n8k16.row.col.f32.f16.f16.f32 "
                 "{%0,%1,%2,%3},{%4,%5,%6,%7},{%8,%9},{%0,%1,%2,%3};"
                 : "+f"(c0), "+f"(c1), "+f"(c2), "+f"(c3)
                 : "r"(a0), "r"(a1), "r"(a2), "r"(a3), "r"(b0), "r"(b1));
}

// ---------------------------------------------------------------------------
// Kernel 1: FUSED proj + attention, fp16 m16n8k16. CTA = (pair, q-half),
// grid 512, occ 3 (85-reg budget; main-loop live set ~70 fits). Phased
// staging (A: keys->Kth, B: values->Vth/Qs) keeps staging live set ~30.
// 6 warps/SMSP to hide the mma->pack->ex2->AV chain.
// ---------------------------------------------------------------------------
#define QSP 12
#define KTP 520
#define VTPW 264
#define SM_QS 0
#define SM_KT (256*QSP)                   // 3072 (u32)
#define SM_VT (SM_KT + 8*KTP)             // 7232
#define SM_W  (SM_VT + 16*VTPW)           // 11456
#define ATTN_SMEM ((SM_W + 3*256) * 4)    // 48896 B

__global__ __launch_bounds__(256, 3) void fused_attn_kernel(
    const float* __restrict__ values, const float* __restrict__ keys,
    const float* __restrict__ Wq, const float* __restrict__ Wk,
    const float* __restrict__ Wv, const float* __restrict__ Wfc)
{
    extern __shared__ uint32_t smu[];
    uint32_t* Qs  = smu + SM_QS;          // [256][12] half2 (this CTA's q-half)
    uint32_t* Kth = smu + SM_KT;          // [8][520]  half2 (d-pairs)
    __half*   Vth = (__half*)(smu + SM_VT); // [16][528] half
    float4* wsq = (float4*)(smu + SM_W);
    float4* wsk = wsq + 64;
    float4* wsv = wsk + 64;

    int tid = threadIdx.x;
    int lane = tid & 31, w = tid >> 5;
    int g = lane >> 2, t = lane & 3;
    int p  = blockIdx.x >> 1;             // pair = tq*HH + hh
    int qb = blockIdx.x & 1;              // q-half
    int hh = p & 7, tq = p >> 3;
    const float cs = 0.08838834764831845f * 1.4426950408889634f; // 1/sqrt(128)*log2e

    // ---- folded one-shot W16 prep (fc consumes next launch) ----
    if (blockIdx.x < 32) {
        int i = blockIdx.x*256 + tid;     // 0..8191
        int cp = i >> 7, e = i & 127;
        g_Wh[i] = packh2(Wfc[e*CC + 2*cp], Wfc[e*CC + 2*cp + 1]);
    }

    if (tid < 64)       wsq[tid]     = ((const float4*)Wq)[tid];
    else if (tid < 128) wsk[tid-64]  = ((const float4*)Wk)[tid-64];
    else if (tid < 192) wsv[tid-128] = ((const float4*)Wv)[tid-128];
    __syncthreads();

    // ---- phase A: keys -> Kth (only Y live) ----
    #pragma unroll
    for (int rr = 0; rr < 2; rr++) {
        int node = tid + rr*256;
        const float4* yin = (const float4*)(keys + (node*TT + tq)*CC + hh*DD);
        float4 Y[4];
        #pragma unroll
        for (int i = 0; i < 4; i++) Y[i] = yin[i];
        #pragma unroll
        for (int dp = 0; dp < 8; dp++) {
            float ak0=0.f, ak1=0.f;
            #pragma unroll
            for (int d4 = 0; d4 < 4; d4++) {
                float4 b0 = wsk[(2*dp  )*4 + d4], b1 = wsk[(2*dp+1)*4 + d4];
                ak0 = fmaf(Y[d4].x,b0.x,ak0); ak0 = fmaf(Y[d4].y,b0.y,ak0);
                ak0 = fmaf(Y[d4].z,b0.z,ak0); ak0 = fmaf(Y[d4].w,b0.w,ak0);
                ak1 = fmaf(Y[d4].x,b1.x,ak1); ak1 = fmaf(Y[d4].y,b1.y,ak1);
                ak1 = fmaf(Y[d4].z,b1.z,ak1); ak1 = fmaf(Y[d4].w,b1.w,ak1);
            }
            Kth[dp*KTP + node] = packh2(ak0, ak1);
        }
    }
    // ---- phase B: values -> Vth (+Qs when rr==qb; only X live) ----
    #pragma unroll
    for (int rr = 0; rr < 2; rr++) {
        int node = tid + rr*256;
        const float4* xin = (const float4*)(values + (node*TT + tq)*CC + hh*DD);
        float4 X[4];
        #pragma unroll
        for (int i = 0; i < 4; i++) X[i] = xin[i];
        #pragma unroll
        for (int dp = 0; dp < 8; dp++) {
            float av0=0.f, av1=0.f;
            #pragma unroll
            for (int d4 = 0; d4 < 4; d4++) {
                float4 c0 = wsv[(2*dp  )*4 + d4], c1 = wsv[(2*dp+1)*4 + d4];
                av0 = fmaf(X[d4].x,c0.x,av0); av0 = fmaf(X[d4].y,c0.y,av0);
                av0 = fmaf(X[d4].z,c0.z,av0); av0 = fmaf(X[d4].w,c0.w,av0);
                av1 = fmaf(X[d4].x,c1.x,av1); av1 = fmaf(X[d4].y,c1.y,av1);
                av1 = fmaf(X[d4].z,c1.z,av1); av1 = fmaf(X[d4].w,c1.w,av1);
            }
            Vth[(2*dp  )*528 + node] = __float2half_rn(av0);
            Vth[(2*dp+1)*528 + node] = __float2half_rn(av1);
        }
        if (rr == qb) {
            #pragma unroll
            for (int dp = 0; dp < 8; dp++) {
                float aq0=0.f, aq1=0.f;
                #pragma unroll
                for (int d4 = 0; d4 < 4; d4++) {
                    float4 a0 = wsq[(2*dp  )*4 + d4], a1 = wsq[(2*dp+1)*4 + d4];
                    aq0 = fmaf(X[d4].x,a0.x,aq0); aq0 = fmaf(X[d4].y,a0.y,aq0);
                    aq0 = fmaf(X[d4].z,a0.z,aq0); aq0 = fmaf(X[d4].w,a0.w,aq0);
                    aq1 = fmaf(X[d4].x,a1.x,aq1); aq1 = fmaf(X[d4].y,a1.y,aq1);
                    aq1 = fmaf(X[d4].z,a1.z,aq1); aq1 = fmaf(X[d4].w,a1.w,aq1);
                }
                Qs[tid*QSP + dp] = packh2(aq0*cs, aq1*cs);
            }
        }
    }
    __syncthreads();

    // ---- Q fragments: warp owns local rows w*32 .. +31 (2 groups of 16) ----
    uint32_t qa[2][4];
    #pragma unroll
    for (int u = 0; u < 2; u++) {
        int base = w*32 + u*16;
        qa[u][0] = Qs[(base+g  )*QSP + t];
        qa[u][1] = Qs[(base+g+8)*QSP + t];
        qa[u][2] = Qs[(base+g  )*QSP + t + 4];
        qa[u][3] = Qs[(base+g+8)*QSP + t + 4];
    }

    float o[2][8];
    uint32_t lacc[2][2];
    #pragma unroll
    for (int u = 0; u < 2; u++) {
        #pragma unroll
        for (int i = 0; i < 8; i++) o[u][i] = 0.f;
        lacc[u][0] = 0u; lacc[u][1] = 0u;
    }

    const uint32_t* Vw = (const uint32_t*)Vth;

    #pragma unroll 2
    for (int tile = 0; tile < 32; tile++) {
        int n0 = tile*16, np0 = tile*8;
        uint32_t kb0 = Kth[(t  )*KTP + n0 + g];
        uint32_t kb1 = Kth[(t+4)*KTP + n0 + g];
        uint32_t kb2 = Kth[(t  )*KTP + n0 + 8 + g];
        uint32_t kb3 = Kth[(t+4)*KTP + n0 + 8 + g];
        uint32_t vb0 = Vw[(g  )*VTPW + np0 + t];
        uint32_t vb1 = Vw[(g  )*VTPW + np0 + t + 4];
        uint32_t vb2 = Vw[(g+8)*VTPW + np0 + t];
        uint32_t vb3 = Vw[(g+8)*VTPW + np0 + t + 4];
        #pragma unroll
        for (int u = 0; u < 2; u++) {
            float f0=0.f,f1=0.f,f2=0.f,f3=0.f;
            float h0=0.f,h1=0.f,h2=0.f,h3=0.f;
            mma_f16(f0,f1,f2,f3, qa[u][0],qa[u][1],qa[u][2],qa[u][3], kb0,kb1);
            mma_f16(h0,h1,h2,h3, qa[u][0],qa[u][1],qa[u][2],qa[u][3], kb2,kb3);
            uint32_t pa0 = ex2h2(packh2(f0,f1));   // row g,   nodes n0+2t,2t+1
            uint32_t pa1 = ex2h2(packh2(f2,f3));   // row g+8
            uint32_t pa2 = ex2h2(packh2(h0,h1));   // row g,   nodes n0+8+2t,..
            uint32_t pa3 = ex2h2(packh2(h2,h3));   // row g+8
            lacc[u][0] = hadd2(lacc[u][0], hadd2(pa0, pa2));
            lacc[u][1] = hadd2(lacc[u][1], hadd2(pa1, pa3));
            mma_f16(o[u][0],o[u][1],o[u][2],o[u][3], pa0,pa1,pa2,pa3, vb0,vb1);
            mma_f16(o[u][4],o[u][5],o[u][6],o[u][7], pa0,pa1,pa2,pa3, vb2,vb3);
        }
    }

    // ---- epilogue: fp32 quad-combine of fp16 partials, normalize, store ----
    #pragma unroll
    for (int u = 0; u < 2; u++) {
        float la = h2sum(lacc[u][0]);
        float lb = h2sum(lacc[u][1]);
        la += __shfl_xor_sync(0xffffffffu, la, 1);
        la += __shfl_xor_sync(0xffffffffu, la, 2);
        lb += __shfl_xor_sync(0xffffffffu, lb, 1);
        lb += __shfl_xor_sync(0xffffffffu, lb, 2);
        float ia = 1.0f / la, ib = 1.0f / lb;
        int node = qb*256 + w*32 + u*16 + g;
        uint32_t* d0 = g_O16 + (node*TT + tq)*(HH*8) + hh*8;
        uint32_t* d1 = d0 + 8*TT*(HH*8);   // node+8 (row stride = HH*8 u32)
        d0[t]   = packh2(o[u][0]*ia, o[u][1]*ia);
        d0[t+4] = packh2(o[u][4]*ia, o[u][5]*ia);
        d1[t]   = packh2(o[u][2]*ib, o[u][3]*ib);
        d1[t+4] = packh2(o[u][6]*ib, o[u][7]*ib);
    }
}

// ---------------------------------------------------------------------------
// Kernel 2: final FC, fp16 mma, single pre-converted W — R9 smem version
// (measured 8.0us). 64 rows/CTA, grid 256, 3 CTAs/SM (54KB smem).
// ---------------------------------------------------------------------------
#define FCWHP 136
#define FCXP 72
#define FC_WH 0
#define FC_X  (64*FCWHP)                      // 8704
#define FC_B  (FC_X + 64*FCXP)                // 13312
#define FC_SMEM ((FC_B + CC) * 4)             // 53760 B

__global__ __launch_bounds__(256, 3) void fc_kernel(
    const float* __restrict__ bfc, float* __restrict__ out)
{
    extern __shared__ uint32_t shu[];
    uint32_t* Whs = shu + FC_WH;              // [64 cp][136 e]
    uint32_t* X16 = shu + FC_X;               // [64 r][72 dpair]
    float*    Bs  = (float*)(shu + FC_B);
    int tid = threadIdx.x;
    int lane = tid & 31, w = tid >> 5;
    int g = lane >> 2, t = lane & 3;
    int row0 = blockIdx.x * 64;

    #pragma unroll
    for (int j = 0; j < 8; j++) {
        int i4 = tid + j*256;                 // 2048 float4
        int cp = i4 >> 5, e4 = (i4 & 31) << 2;
        *(float4*)(Whs + cp*FCWHP + e4) = ((const float4*)g_Wh)[i4];
    }
    #pragma unroll
    for (int j = 0; j < 4; j++) {
        int i4 = tid + j*256;                 // 1024 float4
        int r = i4 >> 4, c4 = (i4 & 15) << 2;
        *(float4*)(X16 + r*FCXP + c4) = *(const float4*)(g_O16 + (row0 + r)*64 + c4);
    }
    if (tid < CC) Bs[tid] = bfc[tid];
    __syncthreads();

    int rg = (w & 3) * 16, eq = (w >> 2) * 64;
    float acc[8][4];
    #pragma unroll
    for (int nt = 0; nt < 8; nt++)
        #pragma unroll
        for (int i = 0; i < 4; i++) acc[nt][i] = 0.f;

    #pragma unroll
    for (int kk = 0; kk < 8; kk++) {
        uint32_t a0 = X16[(rg+g  )*FCXP + kk*8 + t];
        uint32_t a1 = X16[(rg+g+8)*FCXP + kk*8 + t];
        uint32_t a2 = X16[(rg+g  )*FCXP + kk*8 + t + 4];
        uint32_t a3 = X16[(rg+g+8)*FCXP + kk*8 + t + 4];
        #pragma unroll
        for (int nt = 0; nt < 8; nt++) {
            int e0 = eq + nt*8;
            uint32_t bh0 = Whs[(kk*8+t  )*FCWHP + e0 + g];
            uint32_t bh1 = Whs[(kk*8+t+4)*FCWHP + e0 + g];
            mma_f16(acc[nt][0],acc[nt][1],acc[nt][2],acc[nt][3], a0,a1,a2,a3, bh0,bh1);
        }
    }

    #pragma unroll
    for (int nt = 0; nt < 8; nt++) {
        int e = eq + nt*8 + 2*t;
        float b0 = Bs[e], b1 = Bs[e+1];
        int R = row0 + rg + g;
        *(float2*)(out + R*CC + e)     = make_float2(acc[nt][0] + b0, acc[nt][1] + b1);
        *(float2*)(out + (R+8)*CC + e) = make_float2(acc[nt][2] + b0, acc[nt][3] + b1);
    }
}

// ---------------------------------------------------------------------------
extern "C" void kernel_launch(void* const* d_in, const int* in_sizes, int n_in,
                              void* d_out, int out_size)
{
    const float *values = nullptr, *keys = nullptr, *query = nullptr;
    const float *Wq = nullptr, *Wk = nullptr, *Wv = nullptr;
    const float *Wfc = nullptr, *bfc = nullptr;
    for (int i = 0; i < n_in; i++) {
        int sz = in_sizes[i];
        const float* ptr = (const float*)d_in[i];
        if (sz == NN*TT*CC) {
            if (!values) values = ptr; else if (!keys) keys = ptr; else if (!query) query = ptr;
        } else if (sz == DD*DD) {
            if (!Wq) Wq = ptr; else if (!Wk) Wk = ptr; else if (!Wv) Wv = ptr;
        } else if (sz == CC*CC) {
            Wfc = ptr;
        } else if (sz == CC) {
            bfc = ptr;
        }
    }

    cudaFuncSetAttribute(fused_attn_kernel, cudaFuncAttributeMaxDynamicSharedMemorySize, ATTN_SMEM);
    cudaFuncSetAttribute(fc_kernel, cudaFuncAttributeMaxDynamicSharedMemorySize, FC_SMEM);

    fused_attn_kernel<<<TT*HH*2, 256, ATTN_SMEM>>>(values, keys, Wq, Wk, Wv, Wfc);
    fc_kernel<<<(NN*TT)/64, 256, FC_SMEM>>>(bfc, (float*)d_out);
}

// round 16
// speedup vs baseline: 2.0446x; 2.0446x over previous
#include <cuda_runtime.h>
#include <cuda_fp16.h>
#include <cstdint>

#define NN 512          // nodes (attention axis)
#define TT 32           // time steps
#define HH 8            // heads
#define DD 16           // per-head dim
#define CC 128          // embed

// Attention output: [node][t][h][dpair] as half2-in-u32, row-major = [row R][64]
__device__ uint32_t g_O16[NN*TT*HH*8];
// Pre-converted FC weights, B-operand layout [cpair 64][e 128], fp16 pairs
__device__ uint32_t g_Wh[64*CC];

__device__ __forceinline__ uint32_t packh2(float lo, float hi){
    uint32_t r; asm("cvt.rn.f16x2.f32 %0, %1, %2;" : "=r"(r) : "f"(hi), "f"(lo)); return r;
}
__device__ __forceinline__ uint32_t ex2h2(uint32_t x){
    uint32_t r; asm("ex2.approx.f16x2 %0, %1;" : "=r"(r) : "r"(x)); return r;
}
__device__ __forceinline__ uint32_t hadd2(uint32_t a, uint32_t b){
    uint32_t r; asm("add.f16x2 %0, %1, %2;" : "=r"(r) : "r"(a), "r"(b)); return r;
}
__device__ __forceinline__ float h2sum(uint32_t v){
    __half2 h = *(__half2*)&v;
    return __half2float(__low2half(h)) + __half2float(__high2half(h));
}
__device__ __forceinline__ void mma_f16(float& c0, float& c1, float& c2, float& c3,
                                        uint32_t a0, uint32_t a1, uint32_t a2, uint32_t a3,
                                        uint32_t b0, uint32_t b1){
    asm volatile("mma.sync.aligned.m16n8k16.row.col.f32.f16.f16.f32 "
                 "{%0,%1,%2,%3},{%4,%5,%6,%7},{%8,%9},{%0,%1,%2,%3};"
                 : "+f"(c0), "+f"(c1), "+f"(c2), "+f"(c3)
                 : "r"(a0), "r"(a1), "r"(a2), "r"(a3), "r"(b0), "r"(b1));
}

// ---------------------------------------------------------------------------
// Kernel 1: FUSED proj + attention, fp16 m16n8k16. CTA = one (t,h) pair,
// 256 threads, occ 2 (~128-reg budget). q,v from `values` (reference bug),
// k from `keys`. S-mma C-frag == AV A-frag layout (zero shuffles); l via
// add.f16x2 partials; W16 prep for fc folded into CTAs 0..31.
// ---------------------------------------------------------------------------
#define QSP 12
#define KTP 520
#define VTPW 264
#define SM_QS 0
#define SM_KT (512*QSP)                   // u32 index
#define SM_VT (SM_KT + 8*KTP)
#define SM_W  (SM_VT + 16*VTPW)
#define ATTN_SMEM ((SM_W + 3*256) * 4)    // 61184 B

__global__ __launch_bounds__(256, 2) void fused_attn_kernel(
    const float* __restrict__ values, const float* __restrict__ keys,
    const float* __restrict__ Wq, const float* __restrict__ Wk,
    const float* __restrict__ Wv, const float* __restrict__ Wfc)
{
    extern __shared__ uint32_t smu[];
    uint32_t* Qs  = smu + SM_QS;          // [512][12] half2
    uint32_t* Kth = smu + SM_KT;          // [8][520]  half2 (d-pairs)
    __half*   Vth = (__half*)(smu + SM_VT); // [16][528] half
    float4* wsq = (float4*)(smu + SM_W);
    float4* wsk = wsq + 64;
    float4* wsv = wsk + 64;

    int tid = threadIdx.x;
    int lane = tid & 31, w = tid >> 5;
    int g = lane >> 2, t = lane & 3;
    int p  = blockIdx.x;
    int hh = p & 7, tq = p >> 3;
    const float cs = 0.08838834764831845f * 1.4426950408889634f; // 1/sqrt(128)*log2e

    // ---- folded one-shot W16 prep (fc consumes next launch) ----
    if (p < 32) {
        int i = p*256 + tid;              // 0..8191
        int cp = i >> 7, e = i & 127;
        g_Wh[i] = packh2(Wfc[e*CC + 2*cp], Wfc[e*CC + 2*cp + 1]);
    }

    if (tid < 64)       wsq[tid]     = ((const float4*)Wq)[tid];
    else if (tid < 128) wsk[tid-64]  = ((const float4*)Wk)[tid-64];
    else if (tid < 192) wsv[tid-128] = ((const float4*)Wv)[tid-128];
    __syncthreads();

    // ---- staging: project 2 nodes/thread, pack fp16 ----
    #pragma unroll
    for (int rr = 0; rr < 2; rr++) {
        int node = tid + rr*256;
        const float4* xin = (const float4*)(values + (node*TT + tq)*CC + hh*DD);
        const float4* yin = (const float4*)(keys   + (node*TT + tq)*CC + hh*DD);
        float4 X[4], Y[4];
        #pragma unroll
        for (int i = 0; i < 4; i++) { X[i] = xin[i]; Y[i] = yin[i]; }
        #pragma unroll
        for (int dp = 0; dp < 8; dp++) {
            float aq0=0.f, ak0=0.f, av0=0.f, aq1=0.f, ak1=0.f, av1=0.f;
            #pragma unroll
            for (int d4 = 0; d4 < 4; d4++) {
                float4 a0 = wsq[(2*dp  )*4 + d4], a1 = wsq[(2*dp+1)*4 + d4];
                aq0 = fmaf(X[d4].x,a0.x,aq0); aq0 = fmaf(X[d4].y,a0.y,aq0);
                aq0 = fmaf(X[d4].z,a0.z,aq0); aq0 = fmaf(X[d4].w,a0.w,aq0);
                aq1 = fmaf(X[d4].x,a1.x,aq1); aq1 = fmaf(X[d4].y,a1.y,aq1);
                aq1 = fmaf(X[d4].z,a1.z,aq1); aq1 = fmaf(X[d4].w,a1.w,aq1);
                float4 b0 = wsk[(2*dp  )*4 + d4], b1 = wsk[(2*dp+1)*4 + d4];
                ak0 = fmaf(Y[d4].x,b0.x,ak0); ak0 = fmaf(Y[d4].y,b0.y,ak0);
                ak0 = fmaf(Y[d4].z,b0.z,ak0); ak0 = fmaf(Y[d4].w,b0.w,ak0);
                ak1 = fmaf(Y[d4].x,b1.x,ak1); ak1 = fmaf(Y[d4].y,b1.y,ak1);
                ak1 = fmaf(Y[d4].z,b1.z,ak1); ak1 = fmaf(Y[d4].w,b1.w,ak1);
                float4 c0 = wsv[(2*dp  )*4 + d4], c1 = wsv[(2*dp+1)*4 + d4];
                av0 = fmaf(X[d4].x,c0.x,av0); av0 = fmaf(X[d4].y,c0.y,av0);
                av0 = fmaf(X[d4].z,c0.z,av0); av0 = fmaf(X[d4].w,c0.w,av0);
                av1 = fmaf(X[d4].x,c1.x,av1); av1 = fmaf(X[d4].y,c1.y,av1);
                av1 = fmaf(X[d4].z,c1.z,av1); av1 = fmaf(X[d4].w,c1.w,av1);
            }
            Qs[node*QSP + dp]   = packh2(aq0*cs, aq1*cs);
            Kth[dp*KTP + node]  = packh2(ak0, ak1);
            Vth[(2*dp  )*528 + node] = __float2half_rn(av0);
            Vth[(2*dp+1)*528 + node] = __float2half_rn(av1);
        }
    }
    __syncthreads();

    // ---- Q fragments: warp rows w*64 .. +63 ----
    uint32_t qa[4][4];
    #pragma unroll
    for (int u = 0; u < 4; u++) {
        int base = w*64 + u*16;
        qa[u][0] = Qs[(base+g  )*QSP + t];
        qa[u][1] = Qs[(base+g+8)*QSP + t];
        qa[u][2] = Qs[(base+g  )*QSP + t + 4];
        qa[u][3] = Qs[(base+g+8)*QSP + t + 4];
    }

    float o[4][8];
    uint32_t lacc[4][2];
    #pragma unroll
    for (int u = 0; u < 4; u++) {
        #pragma unroll
        for (int i = 0; i < 8; i++) o[u][i] = 0.f;
        lacc[u][0] = 0u; lacc[u][1] = 0u;
    }

    const uint32_t* Vw = (const uint32_t*)Vth;

    #pragma unroll 2
    for (int tile = 0; tile < 32; tile++) {
        int n0 = tile*16, np0 = tile*8;
        uint32_t kb0 = Kth[(t  )*KTP + n0 + g];
        uint32_t kb1 = Kth[(t+4)*KTP + n0 + g];
        uint32_t kb2 = Kth[(t  )*KTP + n0 + 8 + g];
        uint32_t kb3 = Kth[(t+4)*KTP + n0 + 8 + g];
        uint32_t vb0 = Vw[(g  )*VTPW + np0 + t];
        uint32_t vb1 = Vw[(g  )*VTPW + np0 + t + 4];
        uint32_t vb2 = Vw[(g+8)*VTPW + np0 + t];
        uint32_t vb3 = Vw[(g+8)*VTPW + np0 + t + 4];
        #pragma unroll
        for (int u = 0; u < 4; u++) {
            float f0=0.f,f1=0.f,f2=0.f,f3=0.f;
            float h0=0.f,h1=0.f,h2=0.f,h3=0.f;
            mma_f16(f0,f1,f2,f3, qa[u][0],qa[u][1],qa[u][2],qa[u][3], kb0,kb1);
            mma_f16(h0,h1,h2,h3, qa[u][0],qa[u][1],qa[u][2],qa[u][3], kb2,kb3);
            uint32_t pa0 = ex2h2(packh2(f0,f1));   // row g,   nodes n0+2t,2t+1
            uint32_t pa1 = ex2h2(packh2(f2,f3));   // row g+8
            uint32_t pa2 = ex2h2(packh2(h0,h1));   // row g,   nodes n0+8+2t,..
            uint32_t pa3 = ex2h2(packh2(h2,h3));   // row g+8
            lacc[u][0] = hadd2(lacc[u][0], hadd2(pa0, pa2));
            lacc[u][1] = hadd2(lacc[u][1], hadd2(pa1, pa3));
            mma_f16(o[u][0],o[u][1],o[u][2],o[u][3], pa0,pa1,pa2,pa3, vb0,vb1);
            mma_f16(o[u][4],o[u][5],o[u][6],o[u][7], pa0,pa1,pa2,pa3, vb2,vb3);
        }
    }

    // ---- epilogue: fp32 quad-combine of fp16 partials, normalize, store ----
    #pragma unroll
    for (int u = 0; u < 4; u++) {
        float la = h2sum(lacc[u][0]);
        float lb = h2sum(lacc[u][1]);
        la += __shfl_xor_sync(0xffffffffu, la, 1);
        la += __shfl_xor_sync(0xffffffffu, la, 2);
        lb += __shfl_xor_sync(0xffffffffu, lb, 1);
        lb += __shfl_xor_sync(0xffffffffu, lb, 2);
        float ia = 1.0f / la, ib = 1.0f / lb;
        int node = w*64 + u*16 + g;
        uint32_t* d0 = g_O16 + (node*TT + tq)*(HH*8) + hh*8;
        uint32_t* d1 = d0 + 8*TT*(HH*8);   // node+8 (row stride = HH*8 u32)
        d0[t]   = packh2(o[u][0]*ia, o[u][1]*ia);
        d0[t+4] = packh2(o[u][4]*ia, o[u][5]*ia);
        d1[t]   = packh2(o[u][2]*ib, o[u][3]*ib);
        d1[t+4] = packh2(o[u][6]*ib, o[u][7]*ib);
    }
}

// ---------------------------------------------------------------------------
// Kernel 2: final FC, fp16 mma, single pre-converted W. 64 rows/CTA, grid 256,
// 3 CTAs/SM (54KB smem). Staging = pure coalesced copies.
// ---------------------------------------------------------------------------
#define FCWHP 136
#define FCXP 72
#define FC_WH 0
#define FC_X  (64*FCWHP)                      // 8704
#define FC_B  (FC_X + 64*FCXP)                // 13312
#define FC_SMEM ((FC_B + CC) * 4)             // 53760 B

__global__ __launch_bounds__(256, 3) void fc_kernel(
    const float* __restrict__ bfc, float* __restrict__ out)
{
    extern __shared__ uint32_t shu[];
    uint32_t* Whs = shu + FC_WH;              // [64 cp][136 e]
    uint32_t* X16 = shu + FC_X;               // [64 r][72 dpair]
    float*    Bs  = (float*)(shu + FC_B);
    int tid = threadIdx.x;
    int lane = tid & 31, w = tid >> 5;
    int g = lane >> 2, t = lane & 3;
    int row0 = blockIdx.x * 64;

    #pragma unroll
    for (int j = 0; j < 8; j++) {
        int i4 = tid + j*256;                 // 2048 float4
        int cp = i4 >> 5, e4 = (i4 & 31) << 2;
        *(float4*)(Whs + cp*FCWHP + e4) = ((const float4*)g_Wh)[i4];
    }
    #pragma unroll
    for (int j = 0; j < 4; j++) {
        int i4 = tid + j*256;                 // 1024 float4
        int r = i4 >> 4, c4 = (i4 & 15) << 2;
        *(float4*)(X16 + r*FCXP + c4) = *(const float4*)(g_O16 + (row0 + r)*64 + c4);
    }
    if (tid < CC) Bs[tid] = bfc[tid];
    __syncthreads();

    int rg = (w & 3) * 16, eq = (w >> 2) * 64;
    float acc[8][4];
    #pragma unroll
    for (int nt = 0; nt < 8; nt++)
        #pragma unroll
        for (int i = 0; i < 4; i++) acc[nt][i] = 0.f;

    #pragma unroll
    for (int kk = 0; kk < 8; kk++) {
        uint32_t a0 = X16[(rg+g  )*FCXP + kk*8 + t];
        uint32_t a1 = X16[(rg+g+8)*FCXP + kk*8 + t];
        uint32_t a2 = X16[(rg+g  )*FCXP + kk*8 + t + 4];
        uint32_t a3 = X16[(rg+g+8)*FCXP + kk*8 + t + 4];
        #pragma unroll
        for (int nt = 0; nt < 8; nt++) {
            int e0 = eq + nt*8;
            uint32_t bh0 = Whs[(kk*8+t  )*FCWHP + e0 + g];
            uint32_t bh1 = Whs[(kk*8+t+4)*FCWHP + e0 + g];
            mma_f16(acc[nt][0],acc[nt][1],acc[nt][2],acc[nt][3], a0,a1,a2,a3, bh0,bh1);
        }
    }

    #pragma unroll
    for (int nt = 0; nt < 8; nt++) {
        int e = eq + nt*8 + 2*t;
        float b0 = Bs[e], b1 = Bs[e+1];
        int R = row0 + rg + g;
        *(float2*)(out + R*CC + e)     = make_float2(acc[nt][0] + b0, acc[nt][1] + b1);
        *(float2*)(out + (R+8)*CC + e) = make_float2(acc[nt][2] + b0, acc[nt][3] + b1);
    }
}

// ---------------------------------------------------------------------------
extern "C" void kernel_launch(void* const* d_in, const int* in_sizes, int n_in,
                              void* d_out, int out_size)
{
    const float *values = nullptr, *keys = nullptr, *query = nullptr;
    const float *Wq = nullptr, *Wk = nullptr, *Wv = nullptr;
    const float *Wfc = nullptr, *bfc = nullptr;
    for (int i = 0; i < n_in; i++) {
        int sz = in_sizes[i];
        const float* ptr = (const float*)d_in[i];
        if (sz == NN*TT*CC) {
            if (!values) values = ptr; else if (!keys) keys = ptr; else if (!query) query = ptr;
        } else if (sz == DD*DD) {
            if (!Wq) Wq = ptr; else if (!Wk) Wk = ptr; else if (!Wv) Wv = ptr;
        } else if (sz == CC*CC) {
            Wfc = ptr;
        } else if (sz == CC) {
            bfc = ptr;
        }
    }

    cudaFuncSetAttribute(fused_attn_kernel, cudaFuncAttributeMaxDynamicSharedMemorySize, ATTN_SMEM);
    cudaFuncSetAttribute(fc_kernel, cudaFuncAttributeMaxDynamicSharedMemorySize, FC_SMEM);

    fused_attn_kernel<<<TT*HH, 256, ATTN_SMEM>>>(values, keys, Wq, Wk, Wv, Wfc);
    fc_kernel<<<(NN*TT)/64, 256, FC_SMEM>>>(bfc, (float*)d_out);
}